// round 3
// baseline (speedup 1.0000x reference)
#include <cuda_runtime.h>
#include <cstdint>

#define NROWS 8192
#define NCODES 8192
#define HID 256

// Scratch (device globals — no allocation allowed)
__device__ unsigned long long g_min[NROWS];
__device__ float g_hsq[NROWS];
__device__ float g_csq[NCODES];

// ---------------------------------------------------------------------------
// Init per-row argmin keys
// ---------------------------------------------------------------------------
__global__ void init_min_kernel() {
    int i = blockIdx.x * blockDim.x + threadIdx.x;
    if (i < NROWS) g_min[i] = 0xFFFFFFFFFFFFFFFFull;
}

// ---------------------------------------------------------------------------
// Squared norms: one warp per row (h rows then codebook rows)
// ---------------------------------------------------------------------------
__global__ void norms_kernel(const float* __restrict__ h,
                             const float* __restrict__ cb) {
    int warp = (blockIdx.x * blockDim.x + threadIdx.x) >> 5;
    int lane = threadIdx.x & 31;
    const float* p;
    float* outp;
    if (warp < NROWS) {
        p = h + (size_t)warp * HID;
        outp = &g_hsq[warp];
    } else {
        int r = warp - NROWS;
        if (r >= NCODES) return;
        p = cb + (size_t)r * HID;
        outp = &g_csq[r];
    }
    float s = 0.f;
#pragma unroll
    for (int i = lane; i < HID; i += 32) {
        float v = p[i];
        s = fmaf(v, v, s);
    }
#pragma unroll
    for (int o = 16; o; o >>= 1) s += __shfl_xor_sync(0xFFFFFFFFu, s, o);
    if (lane == 0) *outp = s;
}

// ---------------------------------------------------------------------------
// Main: 128x128 register-tiled fp32 GEMM + per-row argmin via atomicMin(u64)
// Block: 256 threads (16x16), 8x8 micro-tile each.
// ---------------------------------------------------------------------------
__global__ __launch_bounds__(256, 2)
void vq_argmin_kernel(const float* __restrict__ h, const float* __restrict__ cb) {
    __shared__ float As[16][132];  // As[k][m] (transposed h tile), pad to avoid conflicts
    __shared__ float Bs[16][132];  // Bs[k][n] (transposed code tile)

    const int t  = threadIdx.x;
    const int tx = t & 15;
    const int ty = t >> 4;
    const int row0 = blockIdx.y * 128;
    const int col0 = blockIdx.x * 128;

    float acc[8][8];
#pragma unroll
    for (int i = 0; i < 8; ++i)
#pragma unroll
        for (int j = 0; j < 8; ++j) acc[i][j] = 0.f;

    for (int kc = 0; kc < HID; kc += 16) {
        // Load 128x16 tiles of h and codebook (transposed into smem)
#pragma unroll
        for (int it = 0; it < 8; ++it) {
            int m = it * 16 + ty;       // 0..127
            int k = tx;                 // 0..15
            As[k][m] = h[(size_t)(row0 + m) * HID + kc + k];
            Bs[k][m] = cb[(size_t)(col0 + m) * HID + kc + k];
        }
        __syncthreads();

#pragma unroll
        for (int k = 0; k < 16; ++k) {
            float4 a0 = *(const float4*)&As[k][ty * 8];
            float4 a1 = *(const float4*)&As[k][ty * 8 + 4];
            float4 b0 = *(const float4*)&Bs[k][tx * 8];
            float4 b1 = *(const float4*)&Bs[k][tx * 8 + 4];
            float a[8] = {a0.x, a0.y, a0.z, a0.w, a1.x, a1.y, a1.z, a1.w};
            float b[8] = {b0.x, b0.y, b0.z, b0.w, b1.x, b1.y, b1.z, b1.w};
#pragma unroll
            for (int i = 0; i < 8; ++i)
#pragma unroll
                for (int j = 0; j < 8; ++j) acc[i][j] = fmaf(a[i], b[j], acc[i][j]);
        }
        __syncthreads();
    }

    // Score = fl(fl(h_sq - 2*dot) + c_sq) — mirror reference rounding structure.
    float hsq[8], csq[8];
#pragma unroll
    for (int i = 0; i < 8; ++i) hsq[i] = g_hsq[row0 + ty * 8 + i];
#pragma unroll
    for (int j = 0; j < 8; ++j) csq[j] = g_csq[col0 + tx * 8 + j];

    unsigned long long best[8];
#pragma unroll
    for (int i = 0; i < 8; ++i) {
        unsigned long long bk = 0xFFFFFFFFFFFFFFFFull;
#pragma unroll
        for (int j = 0; j < 8; ++j) {
            float m2 = __fmul_rn(2.0f, acc[i][j]);
            float tt = __fsub_rn(hsq[i], m2);
            float s  = __fadd_rn(tt, csq[j]);
            unsigned u = __float_as_uint(s);
            u = (u & 0x80000000u) ? ~u : (u | 0x80000000u);  // order-preserving map
            unsigned long long key =
                ((unsigned long long)u << 32) | (unsigned)(col0 + tx * 8 + j);
            if (key < bk) bk = key;
        }
        best[i] = bk;
    }

    // Reduce across the 16 tx lanes sharing each row group (xor<16 stays in-group)
#pragma unroll
    for (int off = 8; off; off >>= 1) {
#pragma unroll
        for (int i = 0; i < 8; ++i) {
            unsigned long long o = __shfl_xor_sync(0xFFFFFFFFu, best[i], off);
            if (o < best[i]) best[i] = o;
        }
    }
    if (tx == 0) {
#pragma unroll
        for (int i = 0; i < 8; ++i)
            atomicMin(&g_min[row0 + ty * 8 + i], best[i]);
    }
}

// ---------------------------------------------------------------------------
// Finalize: one warp per row — scatter one-hot 1.0 and compute loss.
// loss = m + 0.25*m with m = mean((h - z_q)^2), matching reference structure.
// ---------------------------------------------------------------------------
__global__ void finalize_kernel(const float* __restrict__ h,
                                const float* __restrict__ cb,
                                float* __restrict__ out) {
    int warp = (blockIdx.x * blockDim.x + threadIdx.x) >> 5;
    int lane = threadIdx.x & 31;
    if (warp >= NROWS) return;

    unsigned long long key = g_min[warp];
    unsigned idx = (unsigned)(key & 0xFFFFFFFFu);

    const float* hp = h  + (size_t)warp * HID;
    const float* cp = cb + (size_t)idx * HID;
    float s = 0.f;
#pragma unroll
    for (int i = lane; i < HID; i += 32) {
        float d = hp[i] - cp[i];
        s = fmaf(d, d, s);
    }
#pragma unroll
    for (int o = 16; o; o >>= 1) s += __shfl_xor_sync(0xFFFFFFFFu, s, o);

    if (lane == 0) {
        out[(size_t)warp * NCODES + idx] = 1.0f;
        float m = s * (1.0f / (float)HID);  // exact /256
        out[(size_t)NROWS * NCODES + warp] = __fadd_rn(m, __fmul_rn(0.25f, m));
    }
}

// ---------------------------------------------------------------------------
extern "C" void kernel_launch(void* const* d_in, const int* in_sizes, int n_in,
                              void* d_out, int out_size) {
    const float* h  = (const float*)d_in[0];   // (8192, 256)
    // d_in[1] = temperature (unused)
    const float* cb = (const float*)d_in[2];   // (8192, 256)
    float* out = (float*)d_out;                // hard (N*K) then loss (N)

    // Zero the one-hot region (268 MB)
    cudaMemsetAsync(out, 0, (size_t)NROWS * NCODES * sizeof(float));

    init_min_kernel<<<(NROWS + 255) / 256, 256>>>();

    // 16384 warps total (h rows + codebook rows), 8 warps/block
    norms_kernel<<<(NROWS + NCODES) / 8, 256>>>(h, cb);

    dim3 grid(NCODES / 128, NROWS / 128);  // (64, 64)
    vq_argmin_kernel<<<grid, 256>>>(h, cb);

    finalize_kernel<<<NROWS / 8, 256>>>(h, cb, out);
}

// round 5
// speedup vs baseline: 3.1860x; 3.1860x over previous
#include <cuda_runtime.h>
#include <cuda_bf16.h>
#include <cstdint>

#define NROWS 8192
#define NCODES 8192
#define HID 256

// ---------------------------------------------------------------------------
// Device scratch (static globals — allocation-free)
// ---------------------------------------------------------------------------
__device__ __align__(16) __nv_bfloat16 g_hbf[NROWS * HID];
__device__ __align__(16) __nv_bfloat16 g_cbf[NCODES * HID];
__device__ float g_hsq[NROWS];
__device__ float g_csq[NCODES];
__device__ __align__(16) __nv_bfloat16 g_score[(size_t)NROWS * NCODES];  // 128 MB

__device__ __forceinline__ uint32_t smem_u32(const void* p) {
    uint32_t a;
    asm("{ .reg .u64 t; cvta.to.shared.u64 t, %1; cvt.u32.u64 %0, t; }"
        : "=r"(a) : "l"(p));
    return a;
}

#define LDSM_X4(r0, r1, r2, r3, addr)                                         \
    asm volatile("ldmatrix.sync.aligned.m8n8.x4.shared.b16 {%0,%1,%2,%3}, [%4];" \
                 : "=r"(r0), "=r"(r1), "=r"(r2), "=r"(r3) : "r"(addr))

#define MMA16816(d, a0, a1, a2, a3, b0, b1)                                   \
    asm volatile(                                                             \
        "mma.sync.aligned.m16n8k16.row.col.f32.bf16.bf16.f32 "                \
        "{%0,%1,%2,%3}, {%4,%5,%6,%7}, {%8,%9}, {%0,%1,%2,%3};"               \
        : "+f"((d)[0]), "+f"((d)[1]), "+f"((d)[2]), "+f"((d)[3])              \
        : "r"(a0), "r"(a1), "r"(a2), "r"(a3), "r"(b0), "r"(b1))

// ---------------------------------------------------------------------------
// Fused fp32->bf16 convert + squared norms (one warp per row)
// ---------------------------------------------------------------------------
__global__ void convert_norms_kernel(const float* __restrict__ h,
                                     const float* __restrict__ cb) {
    int warp = (blockIdx.x * blockDim.x + threadIdx.x) >> 5;
    int lane = threadIdx.x & 31;
    const float* src;
    __nv_bfloat16* dst;
    float* nrm;
    if (warp < NROWS) {
        src = h + (size_t)warp * HID; dst = g_hbf + (size_t)warp * HID; nrm = &g_hsq[warp];
    } else {
        int r = warp - NROWS;
        if (r >= NCODES) return;
        src = cb + (size_t)r * HID; dst = g_cbf + (size_t)r * HID; nrm = &g_csq[r];
    }
    float s = 0.f;
#pragma unroll
    for (int half = 0; half < 2; ++half) {
        float4 a = ((const float4*)src)[lane + half * 32];
        s = fmaf(a.x, a.x, s); s = fmaf(a.y, a.y, s);
        s = fmaf(a.z, a.z, s); s = fmaf(a.w, a.w, s);
        __nv_bfloat162 p0 = __floats2bfloat162_rn(a.x, a.y);
        __nv_bfloat162 p1 = __floats2bfloat162_rn(a.z, a.w);
        uint2 w;
        w.x = *reinterpret_cast<uint32_t*>(&p0);
        w.y = *reinterpret_cast<uint32_t*>(&p1);
        ((uint2*)dst)[lane + half * 32] = w;
    }
#pragma unroll
    for (int o = 16; o; o >>= 1) s += __shfl_xor_sync(0xFFFFFFFFu, s, o);
    if (lane == 0) *nrm = s;
}

// ---------------------------------------------------------------------------
// bf16 HMMA GEMM (mma.sync.m16n8k16): per CTA 128x128 tile, K=256.
// Writes approx score s = c_sq - 2*dot (bf16) to g_score.
// SMEM: A/B tiles with 528B padded rows (conflict-free ldmatrix);
//       score staging reuses A region with 272B stride (conflict-free stores).
// ---------------------------------------------------------------------------
#define ROW_STRIDE 528               // 512B data + 16B pad
#define SM_A 0
#define SM_B (128 * ROW_STRIDE)      // 67584
#define SM_TOTAL (2 * 128 * ROW_STRIDE)
#define SC_STRIDE 272                // score staging row stride (bytes)

__global__ __launch_bounds__(256, 1) void vq_gemm_kernel() {
    extern __shared__ char smem[];
    const uint32_t sb = smem_u32(smem);
    const int tid = threadIdx.x;
    const int lane = tid & 31;
    const int wid = tid >> 5;
    const int wm = wid & 1;          // warp row (2 x 64)
    const int wn = wid >> 1;         // warp col (4 x 32)
    const int row0 = blockIdx.y * 128;
    const int col0 = blockIdx.x * 128;

    // --- Stage A (h rows) and B (code rows): 128 rows x 512B each ---
#pragma unroll
    for (int i = 0; i < 16; ++i) {
        int idx = tid + i * 256;
        int r = idx >> 5, c = idx & 31;
        uint4 va = *(const uint4*)(g_hbf + (size_t)(row0 + r) * HID + c * 8);
        *(uint4*)(smem + SM_A + r * ROW_STRIDE + c * 16) = va;
        uint4 vb = *(const uint4*)(g_cbf + (size_t)(col0 + r) * HID + c * 8);
        *(uint4*)(smem + SM_B + r * ROW_STRIDE + c * 16) = vb;
    }
    __syncthreads();

    // --- Mainloop: 16 K-steps of k16 ---
    float acc[4][4][4];              // [mi][ni][reg]
#pragma unroll
    for (int mi = 0; mi < 4; ++mi)
#pragma unroll
        for (int ni = 0; ni < 4; ++ni)
#pragma unroll
            for (int q = 0; q < 4; ++q) acc[mi][ni][q] = 0.f;

    const int lrow = lane & 15;      // ldmatrix row within 16
    const int lkc  = lane >> 4;      // ldmatrix k-chunk (0/1)
    const uint32_t aAddr0 = sb + SM_A + (wm * 64 + lrow) * ROW_STRIDE + lkc * 16;
    const uint32_t bAddr0 = sb + SM_B + (wn * 32 + lrow) * ROW_STRIDE + lkc * 16;

#pragma unroll 4
    for (int ks = 0; ks < 16; ++ks) {
        const uint32_t koff = (uint32_t)ks * 32;  // 16 bf16 = 32B
        uint32_t a[4][4], b[2][4];
#pragma unroll
        for (int mi = 0; mi < 4; ++mi)
            LDSM_X4(a[mi][0], a[mi][1], a[mi][2], a[mi][3],
                    aAddr0 + mi * 16 * ROW_STRIDE + koff);
#pragma unroll
        for (int nj = 0; nj < 2; ++nj)
            LDSM_X4(b[nj][0], b[nj][1], b[nj][2], b[nj][3],
                    bAddr0 + nj * 16 * ROW_STRIDE + koff);
#pragma unroll
        for (int mi = 0; mi < 4; ++mi) {
#pragma unroll
            for (int nj = 0; nj < 2; ++nj) {
                // x4 regs: r0=(n0-7,k0-7) r1=(n8-15,k0-7) r2=(n0-7,k8-15) r3=(n8-15,k8-15)
                MMA16816(acc[mi][2 * nj],     a[mi][0], a[mi][1], a[mi][2], a[mi][3],
                         b[nj][0], b[nj][2]);
                MMA16816(acc[mi][2 * nj + 1], a[mi][0], a[mi][1], a[mi][2], a[mi][3],
                         b[nj][1], b[nj][3]);
            }
        }
    }
    __syncthreads();  // done reading A/B smem — about to overwrite with scores

    // --- Epilogue: score = csq - 2*acc, pack bf16x2, stage in smem ---
    float2 csq2[4];
#pragma unroll
    for (int ni = 0; ni < 4; ++ni)
        csq2[ni] = *(const float2*)&g_csq[col0 + wn * 32 + ni * 8 + 2 * (lane & 3)];

    const int erow = wm * 64 + (lane >> 2);
    const int ecol = wn * 32 + 2 * (lane & 3);
#pragma unroll
    for (int mi = 0; mi < 4; ++mi) {
#pragma unroll
        for (int ni = 0; ni < 4; ++ni) {
            float s0 = csq2[ni].x - 2.0f * acc[mi][ni][0];
            float s1 = csq2[ni].y - 2.0f * acc[mi][ni][1];
            float s2 = csq2[ni].x - 2.0f * acc[mi][ni][2];
            float s3 = csq2[ni].y - 2.0f * acc[mi][ni][3];
            __nv_bfloat162 p01 = __floats2bfloat162_rn(s0, s1);
            __nv_bfloat162 p23 = __floats2bfloat162_rn(s2, s3);
            int r = erow + mi * 16;
            int cbyte = (ecol + ni * 8) * 2;
            *(uint32_t*)(smem + r * SC_STRIDE + cbyte) =
                *reinterpret_cast<uint32_t*>(&p01);
            *(uint32_t*)(smem + (r + 8) * SC_STRIDE + cbyte) =
                *reinterpret_cast<uint32_t*>(&p23);
        }
    }
    __syncthreads();

    // --- Coalesced copy-out: 128 rows x 256B ---
#pragma unroll
    for (int i = 0; i < 8; ++i) {
        int idx = tid + i * 256;
        int r = idx >> 4, q = idx & 15;
        uint4 v = *(const uint4*)(smem + r * SC_STRIDE + q * 16);
        *(uint4*)(g_score + (size_t)(row0 + r) * NCODES + col0 + q * 8) = v;
    }
}

// ---------------------------------------------------------------------------
// Select: per row, scan bf16 scores, candidates within EPS of min,
// exact fp32 rescore (reference rounding), one-hot scatter + loss.
// ---------------------------------------------------------------------------
#define EPS 1.0f
#define MAXC 256

__global__ __launch_bounds__(256) void select_kernel(const float* __restrict__ h,
                                                     const float* __restrict__ cb,
                                                     float* __restrict__ out) {
    const int row = blockIdx.x;
    const int tid = threadIdx.x;
    const int wid = tid >> 5;
    const int lane = tid & 31;

    __shared__ float sh[HID];
    __shared__ float wmin[8];
    __shared__ float sthr;
    __shared__ int scand[MAXC];
    __shared__ int scnt;
    __shared__ unsigned long long skey;

    if (tid == 0) { scnt = 0; skey = 0xFFFFFFFFFFFFFFFFull; }
    sh[tid] = h[(size_t)row * HID + tid];

    const uint4* srow = (const uint4*)(g_score + (size_t)row * NCODES);
    uint4 v[4];
    float lmin = 3.4e38f;
#pragma unroll
    for (int i = 0; i < 4; ++i) {
        v[i] = srow[tid + i * 256];
        const uint32_t* u = &v[i].x;
#pragma unroll
        for (int q = 0; q < 4; ++q) {
            float2 f = __bfloat1622float2(*reinterpret_cast<const __nv_bfloat162*>(&u[q]));
            lmin = fminf(lmin, fminf(f.x, f.y));
        }
    }
#pragma unroll
    for (int o = 16; o; o >>= 1) lmin = fminf(lmin, __shfl_xor_sync(0xFFFFFFFFu, lmin, o));
    if (lane == 0) wmin[wid] = lmin;
    __syncthreads();
    if (tid == 0) {
        float m = wmin[0];
#pragma unroll
        for (int i = 1; i < 8; ++i) m = fminf(m, wmin[i]);
        sthr = m + EPS;
    }
    __syncthreads();
    const float thr = sthr;

    // collect candidates
#pragma unroll
    for (int i = 0; i < 4; ++i) {
        const uint32_t* u = &v[i].x;
        int cbase = (tid + i * 256) * 8;
#pragma unroll
        for (int q = 0; q < 4; ++q) {
            float2 f = __bfloat1622float2(*reinterpret_cast<const __nv_bfloat162*>(&u[q]));
            if (f.x < thr) { int p = atomicAdd(&scnt, 1); if (p < MAXC) scand[p] = cbase + 2 * q; }
            if (f.y < thr) { int p = atomicAdd(&scnt, 1); if (p < MAXC) scand[p] = cbase + 2 * q + 1; }
        }
    }
    __syncthreads();

    const float hsq = g_hsq[row];
    const int nc = min(scnt, MAXC);
    for (int ci = wid; ci < nc; ci += 8) {
        int c = scand[ci];
        const float* cp = cb + (size_t)c * HID;
        float dot = 0.f;
#pragma unroll
        for (int k = lane; k < HID; k += 32) dot = fmaf(sh[k], cp[k], dot);
#pragma unroll
        for (int o = 16; o; o >>= 1) dot += __shfl_xor_sync(0xFFFFFFFFu, dot, o);
        if (lane == 0) {
            float s = __fadd_rn(__fsub_rn(hsq, __fmul_rn(2.0f, dot)), g_csq[c]);
            unsigned u = __float_as_uint(s);
            u = (u & 0x80000000u) ? ~u : (u | 0x80000000u);
            atomicMin(&skey, ((unsigned long long)u << 32) | (unsigned)c);
        }
    }
    __syncthreads();

    if (wid == 0) {
        unsigned idx = (unsigned)(skey & 0xFFFFFFFFu);
        const float* cp = cb + (size_t)idx * HID;
        float s = 0.f;
#pragma unroll
        for (int k = lane; k < HID; k += 32) {
            float d = sh[k] - cp[k];
            s = fmaf(d, d, s);
        }
#pragma unroll
        for (int o = 16; o; o >>= 1) s += __shfl_xor_sync(0xFFFFFFFFu, s, o);
        if (lane == 0) {
            out[(size_t)row * NCODES + idx] = 1.0f;
            float m = s * (1.0f / (float)HID);
            out[(size_t)NROWS * NCODES + row] = __fadd_rn(m, __fmul_rn(0.25f, m));
        }
    }
}

// ---------------------------------------------------------------------------
extern "C" void kernel_launch(void* const* d_in, const int* in_sizes, int n_in,
                              void* d_out, int out_size) {
    const float* h  = (const float*)d_in[0];   // (8192, 256)
    const float* cb = (const float*)d_in[2];   // (8192, 256)
    float* out = (float*)d_out;

    static bool attr_set = false;
    if (!attr_set) {
        cudaFuncSetAttribute(vq_gemm_kernel,
                             cudaFuncAttributeMaxDynamicSharedMemorySize, SM_TOTAL);
        attr_set = true;
    }

    // Zero the one-hot region (268 MB)
    cudaMemsetAsync(out, 0, (size_t)NROWS * NCODES * sizeof(float));

    convert_norms_kernel<<<(NROWS + NCODES) / 8, 256>>>(h, cb);

    dim3 grid(NCODES / 128, NROWS / 128);  // (64, 64)
    vq_gemm_kernel<<<grid, 256, SM_TOTAL>>>();

    select_kernel<<<NROWS, 256>>>(h, cb, out);
}